// round 1
// baseline (speedup 1.0000x reference)
#include <cuda_runtime.h>
#include <cstdint>

#define D 200
#define NREL 474
#define NTAB 948        // 2*NREL
#define GEMM_ROWS 16
#define BN_ROWS 250

// ---- scratch (__device__ globals; no cudaMalloc allowed) ----
__device__ __align__(16) float g_Mtab[NTAB * D];   // softmax(rel@W)/3 tables
__device__ __align__(16) float g_Weff[D * D];      // (circulant(loop_rel) @ loop_w)/3
__device__ float g_sum[D];
__device__ float g_sumsq[D];
__device__ float g_scale[D];
__device__ float g_shift[D];

// ---- packed f32x2 helpers (FFMA2: 2 MACs/instr, PTX-only pattern) ----
__device__ __forceinline__ unsigned long long fma2(unsigned long long a,
                                                   unsigned long long b,
                                                   unsigned long long c) {
    unsigned long long d;
    asm("fma.rn.f32x2 %0, %1, %2, %3;" : "=l"(d) : "l"(a), "l"(b), "l"(c));
    return d;
}
__device__ __forceinline__ unsigned long long pack2(float lo, float hi) {
    unsigned long long d;
    asm("mov.b64 %0, {%1, %2};" : "=l"(d) : "f"(lo), "f"(hi));
    return d;
}
__device__ __forceinline__ void unpack2(unsigned long long v, float& lo, float& hi) {
    asm("mov.b64 {%0, %1}, %2;" : "=f"(lo), "=f"(hi) : "l"(v));
}

// ============================================================================
// prep: builds g_Mtab (948 softmaxed message rows), g_Weff (circulant-folded
// self-loop weight), and writes rel_out = rel_repr @ w_rel. Also zeroes BN stats.
// grid = NTAB + D + NREL blocks, 256 threads.
// ============================================================================
__global__ void prep_kernel(const float* __restrict__ rel_repr,
                            const float* __restrict__ in_w,
                            const float* __restrict__ out_w,
                            const float* __restrict__ loop_w,
                            const float* __restrict__ w_rel,
                            const float* __restrict__ loop_rel,
                            float* __restrict__ rel_out) {
    __shared__ float rs[D];
    __shared__ float red[256];
    int b = blockIdx.x, tid = threadIdx.x;
    if (b == 0 && tid < D) { g_sum[tid] = 0.f; g_sumsq[tid] = 0.f; }

    if (b < NTAB) {
        int t = (b < NREL) ? b : b - NREL;
        const float* W = (b < NREL) ? in_w : out_w;
        if (tid < D) rs[tid] = rel_repr[t * D + tid];
        __syncthreads();
        float acc = 0.f;
        if (tid < D) {
            #pragma unroll 4
            for (int k = 0; k < D; k++) acc = fmaf(rs[k], W[k * D + tid], acc);
        }
        // softmax over the 200 outputs (one value per thread)
        red[tid] = (tid < D) ? acc : -1e30f;
        __syncthreads();
        for (int s = 128; s > 0; s >>= 1) {
            if (tid < s) red[tid] = fmaxf(red[tid], red[tid + s]);
            __syncthreads();
        }
        float mx = red[0];
        __syncthreads();
        float e = (tid < D) ? expf(acc - mx) : 0.f;
        red[tid] = e;
        __syncthreads();
        for (int s = 128; s > 0; s >>= 1) {
            if (tid < s) red[tid] += red[tid + s];
            __syncthreads();
        }
        float inv = 1.f / (red[0] * 3.f);   // fold the /3 of apply_node into table
        if (tid < D) g_Mtab[b * D + tid] = e * inv;
    } else if (b < NTAB + D) {
        // Weff[k][j] = sum_m loop_rel[(m+k)%D] * loop_w[m][j] / 3
        int kk = b - NTAB;
        if (tid < D) rs[tid] = loop_rel[tid];
        __syncthreads();
        if (tid < D) {
            float acc = 0.f;
            #pragma unroll 4
            for (int m = 0; m < D; m++) {
                int mm = m + kk; if (mm >= D) mm -= D;
                acc = fmaf(rs[mm], loop_w[m * D + tid], acc);
            }
            g_Weff[kk * D + tid] = acc * (1.f / 3.f);
        }
    } else {
        // rel_out = rel_repr @ w_rel
        int t = b - (NTAB + D);
        if (tid < D) rs[tid] = rel_repr[t * D + tid];
        __syncthreads();
        if (tid < D) {
            float acc = 0.f;
            #pragma unroll 4
            for (int k = 0; k < D; k++) acc = fmaf(rs[k], w_rel[k * D + tid], acc);
            rel_out[t * D + tid] = acc;
        }
    }
}

// ============================================================================
// loop_gemm: out[v] = x[v] @ Weff + bias  (self-loop branch, /3 already in Weff)
// Weff fully resident in shared (160KB); 16 rows/block; each thread owns a
// 4-row x 4-col tile accumulated with packed fma.rn.f32x2.
// ============================================================================
__global__ void loop_gemm_kernel(const float* __restrict__ x,
                                 const float* __restrict__ bias,
                                 float* __restrict__ out) {
    extern __shared__ float sm[];
    float* Ws = sm;                 // D*D
    float* xs = sm + D * D;         // GEMM_ROWS*D
    int tid = threadIdx.x;
    for (int i = tid; i < D * D; i += 256) Ws[i] = g_Weff[i];
    int row0 = blockIdx.x * GEMM_ROWS;
    for (int i = tid; i < GEMM_ROWS * D; i += 256) xs[i] = x[(size_t)row0 * D + i];
    __syncthreads();

    int cg = tid & 63, team = tid >> 6;  // 4 teams x (50 active colgroups)
    if (cg < 50) {
        int j0 = cg * 4;
        unsigned long long a01[4], a23[4];
        #pragma unroll
        for (int r = 0; r < 4; r++) { a01[r] = 0ull; a23[r] = 0ull; }
        const float* xrow = xs + team * 4 * D;
        #pragma unroll 2
        for (int k = 0; k < D; k++) {
            float4 w = *reinterpret_cast<const float4*>(Ws + k * D + j0);
            unsigned long long w01 = pack2(w.x, w.y);
            unsigned long long w23 = pack2(w.z, w.w);
            #pragma unroll
            for (int r = 0; r < 4; r++) {
                float xv = xrow[r * D + k];
                unsigned long long xx = pack2(xv, xv);
                a01[r] = fma2(xx, w01, a01[r]);
                a23[r] = fma2(xx, w23, a23[r]);
            }
        }
        float b0 = bias[j0], b1 = bias[j0 + 1], b2 = bias[j0 + 2], b3 = bias[j0 + 3];
        #pragma unroll
        for (int r = 0; r < 4; r++) {
            float v0, v1, v2, v3;
            unpack2(a01[r], v0, v1);
            unpack2(a23[r], v2, v3);
            float4 o = make_float4(v0 + b0, v1 + b1, v2 + b2, v3 + b3);
            *reinterpret_cast<float4*>(out + (size_t)(row0 + team * 4 + r) * D + j0) = o;
        }
    }
}

// ============================================================================
// scatter: out[dst[e]] += Mtab[row(e)] * edge_norm[e]   (vector atomics)
// one thread per (edge, float4-chunk): 50M red.global.add.v4.f32
// ============================================================================
__global__ void scatter_kernel(const int* __restrict__ edge_type,
                               const int* __restrict__ dst,
                               const float* __restrict__ edge_norm,
                               float* __restrict__ out, int E, int half) {
    int i = blockIdx.x * 256 + threadIdx.x;
    if (i >= E * 50) return;
    int e = i / 50;
    int c = i - e * 50;
    int t = edge_type[e];
    int row = (e < half) ? t : t + NREL;
    float n = edge_norm[e];
    float4 m = *reinterpret_cast<const float4*>(g_Mtab + row * D + c * 4);
    float* p = out + (size_t)dst[e] * D + c * 4;
    asm volatile("red.global.add.v4.f32 [%0], {%1, %2, %3, %4};"
                 :: "l"(p), "f"(m.x * n), "f"(m.y * n), "f"(m.z * n), "f"(m.w * n)
                 : "memory");
}

// ============================================================================
// BatchNorm: column stats (coalesced register reduce -> 2 global atomics/thread)
// ============================================================================
__global__ void bn_reduce_kernel(const float* __restrict__ out) {
    int j = threadIdx.x;                       // blockDim = 200 = D
    int v0 = blockIdx.x * BN_ROWS;
    float s = 0.f, q = 0.f;
    const float* p = out + (size_t)v0 * D + j;
    #pragma unroll 4
    for (int r = 0; r < BN_ROWS; r++) {
        float v = p[(size_t)r * D];
        s += v; q += v * v;
    }
    atomicAdd(&g_sum[j], s);
    atomicAdd(&g_sumsq[j], q);
}

__global__ void bn_params_kernel(const float* __restrict__ bn_w,
                                 const float* __restrict__ bn_b, float invV) {
    int j = threadIdx.x;
    if (j < D) {
        float mean = g_sum[j] * invV;
        float var = g_sumsq[j] * invV - mean * mean;   // biased variance
        float sc = bn_w[j] * rsqrtf(var + 1e-5f);
        g_scale[j] = sc;
        g_shift[j] = bn_b[j] - mean * sc;
    }
}

__global__ void bn_final_kernel(float* __restrict__ out, int total4) {
    int i = blockIdx.x * 256 + threadIdx.x;    // float4 index
    if (i >= total4) return;
    int c0 = (i % 50) * 4;
    float4 v = reinterpret_cast<float4*>(out)[i];
    v.x = v.x * g_scale[c0]     + g_shift[c0];
    v.y = v.y * g_scale[c0 + 1] + g_shift[c0 + 1];
    v.z = v.z * g_scale[c0 + 2] + g_shift[c0 + 2];
    v.w = v.w * g_scale[c0 + 3] + g_shift[c0 + 3];
    reinterpret_cast<float4*>(out)[i] = v;
}

// ============================================================================
extern "C" void kernel_launch(void* const* d_in, const int* in_sizes, int n_in,
                              void* d_out, int out_size) {
    const float* x         = (const float*)d_in[0];
    const float* rel_repr  = (const float*)d_in[1];
    const float* edge_norm = (const float*)d_in[2];
    const float* in_w      = (const float*)d_in[3];
    const float* out_w     = (const float*)d_in[4];
    const float* loop_w    = (const float*)d_in[5];
    const float* w_rel     = (const float*)d_in[6];
    const float* loop_rel  = (const float*)d_in[7];
    const float* bias      = (const float*)d_in[8];
    const float* bn_w      = (const float*)d_in[9];
    const float* bn_b      = (const float*)d_in[10];
    const int*   edge_type = (const int*)d_in[11];
    const int*   dst       = (const int*)d_in[12];
    float* out = (float*)d_out;

    int V = in_sizes[0] / D;           // 100000
    int E = in_sizes[2];               // 1000000
    float* rel_out = out + (size_t)V * D;

    size_t smem = (size_t)(D * D + GEMM_ROWS * D) * sizeof(float);   // 172.8 KB
    cudaFuncSetAttribute(loop_gemm_kernel,
                         cudaFuncAttributeMaxDynamicSharedMemorySize, (int)smem);

    // 1. tables + Weff + rel_out (+ zero BN stats)
    prep_kernel<<<NTAB + D + NREL, 256>>>(rel_repr, in_w, out_w, loop_w,
                                          w_rel, loop_rel, rel_out);
    // 2. self-loop GEMM writes out = x@Weff + bias (initializes output region)
    loop_gemm_kernel<<<V / GEMM_ROWS, 256, smem>>>(x, bias, out);
    // 3. edge messages scattered on top with vector atomics
    int nscatter = (E * 50 + 255) / 256;
    scatter_kernel<<<nscatter, 256>>>(edge_type, dst, edge_norm, out, E, E / 2);
    // 4. batchnorm (training-mode batch stats)
    bn_reduce_kernel<<<V / BN_ROWS, D>>>(out);
    bn_params_kernel<<<1, 256>>>(bn_w, bn_b, 1.f / (float)V);
    int total4 = V * (D / 4);
    bn_final_kernel<<<(total4 + 255) / 256, 256>>>(out, total4);
}